// round 14
// baseline (speedup 1.0000x reference)
#include <cuda_runtime.h>
#include <cuda_fp16.h>
#include <math.h>
#include <stdint.h>

#define SEQ 2048
#define BATCH 2
#define ROWS (BATCH*SEQ)   // 4096
#define NHEADS 16
#define QHD 192
#define NOPE 128
#define VHD 128

// ---------------- scratch (device globals; no allocation allowed) ----------------
__device__ float g_qab [(size_t)ROWS*2112];    // [qlora(1536) | ckv(512) | kpe(64)] fp32
__device__ __half g_hs16 [(size_t)ROWS*2048];
__device__ __half g_wab16[(size_t)2112*2048];
__device__ __half g_wqb16[(size_t)3072*1536];
__device__ __half g_wkvb16[(size_t)4096*512];
__device__ __half g_wo16 [(size_t)2048*2048];
__device__ __half g_qlora16[(size_t)ROWS*1536];
__device__ __half g_cnorm16[(size_t)ROWS*512];
__device__ __half g_q16 [(size_t)ROWS*3072];
__device__ __half g_kv16[(size_t)ROWS*4096];
__device__ __half g_kpe16[(size_t)ROWS*64];
__device__ __half g_attn16[(size_t)ROWS*2048];

__device__ __forceinline__ void mma_f16(float d[4], const uint32_t a[4],
                                        const uint32_t b[2]) {
    asm volatile(
        "mma.sync.aligned.m16n8k16.row.col.f32.f16.f16.f32 "
        "{%0,%1,%2,%3}, {%4,%5,%6,%7}, {%8,%9}, {%0,%1,%2,%3};"
        : "+f"(d[0]), "+f"(d[1]), "+f"(d[2]), "+f"(d[3])
        : "r"(a[0]), "r"(a[1]), "r"(a[2]), "r"(a[3]), "r"(b[0]), "r"(b[1]));
}

__device__ __forceinline__ void cp_async16(uint32_t saddr, const void* gptr, bool pred) {
    int sz = pred ? 16 : 0;
    asm volatile("cp.async.cg.shared.global [%0], [%1], 16, %2;\n"
                 :: "r"(saddr), "l"(gptr), "r"(sz));
}

// ---------------- single merged fp32->fp16 conversion over all 6 buffers ----------------
#define CVT_E0 ((size_t)ROWS*2048)
#define CVT_E1 (CVT_E0 + (size_t)1536*2048)
#define CVT_E2 (CVT_E1 + (size_t)576*2048)
#define CVT_E3 (CVT_E2 + (size_t)3072*1536)
#define CVT_E4 (CVT_E3 + (size_t)4096*512)
#define CVT_E5 (CVT_E4 + (size_t)2048*2048)
#define CVT_BLOCKS ((int)(CVT_E5 / 4 / 256))

__global__ __launch_bounds__(256) void cvt_all_k(const float* __restrict__ hs,
                                                 const float* __restrict__ wqa,
                                                 const float* __restrict__ wkva,
                                                 const float* __restrict__ wqb,
                                                 const float* __restrict__ wkvb,
                                                 const float* __restrict__ wo) {
    size_t i = ((size_t)blockIdx.x * 256 + threadIdx.x) * 4;
    const float* src; __half* dst; size_t off;
    if (i < CVT_E0)      { src = hs;   dst = g_hs16;   off = i; }
    else if (i < CVT_E1) { src = wqa;  dst = g_wab16;  off = i - CVT_E0; }
    else if (i < CVT_E2) { src = wkva; dst = g_wab16 + (size_t)1536*2048; off = i - CVT_E1; }
    else if (i < CVT_E3) { src = wqb;  dst = g_wqb16;  off = i - CVT_E2; }
    else if (i < CVT_E4) { src = wkvb; dst = g_wkvb16; off = i - CVT_E3; }
    else                 { src = wo;   dst = g_wo16;   off = i - CVT_E4; }
    float4 v = *(const float4*)(src + off);
    half2* y2 = (half2*)(dst + off);
    y2[0] = __floats2half2_rn(v.x, v.y);
    y2[1] = __floats2half2_rn(v.z, v.w);
}

// ==================================================================
// FP16 dual-GEMM: up to two independent C = A @ B^T in ONE launch.
// 128x128 tile, BK=64, 3-stage cp.async, 256 threads (8 warps 4m x 2n,
// warp tile 32x64), 2 CTAs/SM for latency hiding. mode: 0=fp32 out,
// 2=fp16 out. M % 128 == 0; N guarded.
// ==================================================================
#define HP 72
#define AT_H (128*HP)
#define BT_H (128*HP)
#define ST_H (AT_H + BT_H)
#define GEMM_SMEM (3*ST_H*2)   // 110,592 B -> 2 CTAs/SM

__global__ __launch_bounds__(256, 2) void gemm_dual(
    const __half* __restrict__ A0, const __half* __restrict__ B0,
    void* __restrict__ C0, int N0, int K0, int mode0, int nx0,
    const __half* __restrict__ A1, const __half* __restrict__ B1,
    void* __restrict__ C1, int N1, int K1, int mode1)
{
    extern __shared__ __half smh[];
    const int tid = threadIdx.x;
    const int warp = tid >> 5, lane = tid & 31;
    const int wm = (warp & 3) * 32, wn = (warp >> 2) * 64;
    const int g = lane >> 2, tl = lane & 3;

    const bool second = ((int)blockIdx.x >= nx0);
    const __half* A = second ? A1 : A0;
    const __half* B = second ? B1 : B0;
    void* C   = second ? C1 : C0;
    const int N    = second ? N1 : N0;
    const int K    = second ? K1 : K0;
    const int mode = second ? mode1 : mode0;
    const int m0 = blockIdx.y * 128;
    const int n0 = (second ? (int)blockIdx.x - nx0 : (int)blockIdx.x) * 128;

    float acc[2][8][4];
    #pragma unroll
    for (int i = 0; i < 2; i++)
        #pragma unroll
        for (int j = 0; j < 8; j++)
            #pragma unroll
            for (int v = 0; v < 4; v++) acc[i][j][v] = 0.f;

    const int T = K / 64;

    auto issue = [&](int stage, int t) {
        const int k0 = t * 64;
        uint32_t ab = (uint32_t)__cvta_generic_to_shared(smh + stage * ST_H);
        uint32_t bb = ab + AT_H * 2;
        #pragma unroll
        for (int u = 0; u < 4; u++) {
            int seg = tid + u * 256;
            int row = seg >> 3, gq = (seg & 7) * 8;
            cp_async16(ab + (row * HP + gq) * 2,
                       A + (size_t)(m0 + row) * K + k0 + gq, true);
            int nr = n0 + row;
            cp_async16(bb + (row * HP + gq) * 2,
                       B + (size_t)(nr < N ? nr : 0) * K + k0 + gq, nr < N);
        }
        asm volatile("cp.async.commit_group;");
    };

    issue(0, 0);
    if (T > 1) issue(1, 1); else asm volatile("cp.async.commit_group;");

    for (int t = 0; t < T; t++) {
        asm volatile("cp.async.wait_group 1;");
        __syncthreads();
        if (t + 2 < T) issue((t + 2) % 3, t + 2);
        else asm volatile("cp.async.commit_group;");

        const __half* Ab = smh + (t % 3) * ST_H;
        const __half* Bb = Ab + AT_H;
        #pragma unroll
        for (int ks = 0; ks < 4; ks++) {
            const int kb = ks * 16;
            uint32_t afr[2][4], bfr[8][2];
            #pragma unroll
            for (int mt = 0; mt < 2; mt++) {
                int rb = wm + mt * 16 + g;
                afr[mt][0] = *(const uint32_t*)&Ab[rb * HP + kb + 2 * tl];
                afr[mt][1] = *(const uint32_t*)&Ab[(rb + 8) * HP + kb + 2 * tl];
                afr[mt][2] = *(const uint32_t*)&Ab[rb * HP + kb + 8 + 2 * tl];
                afr[mt][3] = *(const uint32_t*)&Ab[(rb + 8) * HP + kb + 8 + 2 * tl];
            }
            #pragma unroll
            for (int nt = 0; nt < 8; nt++) {
                int cb = wn + nt * 8 + g;
                bfr[nt][0] = *(const uint32_t*)&Bb[cb * HP + kb + 2 * tl];
                bfr[nt][1] = *(const uint32_t*)&Bb[cb * HP + kb + 8 + 2 * tl];
            }
            #pragma unroll
            for (int mt = 0; mt < 2; mt++)
                #pragma unroll
                for (int nt = 0; nt < 8; nt++)
                    mma_f16(acc[mt][nt], afr[mt], bfr[nt]);
        }
    }

    #pragma unroll
    for (int mt = 0; mt < 2; mt++) {
        int r0 = m0 + wm + mt * 16 + g;
        #pragma unroll
        for (int nt = 0; nt < 8; nt++) {
            int cn = n0 + wn + nt * 8 + 2 * tl;
            if (cn < N) {
                float v0 = acc[mt][nt][0], v1 = acc[mt][nt][1];
                float v2 = acc[mt][nt][2], v3 = acc[mt][nt][3];
                if (mode == 2) {
                    __half* Ch = (__half*)C;
                    *(half2*)&Ch[(size_t)r0 * N + cn]       = __floats2half2_rn(v0, v1);
                    *(half2*)&Ch[(size_t)(r0 + 8) * N + cn] = __floats2half2_rn(v2, v3);
                } else {
                    float* Cf = (float*)C;
                    *(float2*)&Cf[(size_t)r0 * N + cn]       = make_float2(v0, v1);
                    *(float2*)&Cf[(size_t)(r0 + 8) * N + cn] = make_float2(v2, v3);
                }
            }
        }
    }
}

// ---------------- merged RMSNorm: y=0 -> qlora(1536), y=1 -> ckv(512) ----------------
__global__ __launch_bounds__(256) void rmsnorm2_k(const float* __restrict__ qab,
                                                  const float* __restrict__ w0,
                                                  const float* __restrict__ w1) {
    int row = blockIdx.x;
    int which = blockIdx.y;
    const float* x = qab + (size_t)row * 2112 + (which ? 1536 : 0);
    const float* w = which ? w1 : w0;
    int W = which ? 512 : 1536;
    __half* Y = which ? (g_cnorm16 + (size_t)row * 512)
                      : (g_qlora16 + (size_t)row * 1536);
    float ss = 0.f;
    for (int i = threadIdx.x; i < W; i += 256) { float v = x[i]; ss += v * v; }
    __shared__ float red[256];
    red[threadIdx.x] = ss;
    __syncthreads();
    for (int s = 128; s > 0; s >>= 1) {
        if (threadIdx.x < s) red[threadIdx.x] += red[threadIdx.x + s];
        __syncthreads();
    }
    float inv = rsqrtf(red[0] / (float)W + 1e-6f);
    for (int i = threadIdx.x; i < W; i += 256)
        Y[i] = __float2half_rn(w[i] * (x[i] * inv));
}

// ---------------- YaRN RoPE (fp16 q in place; kpe fp32->fp16) ----------------
__global__ __launch_bounds__(544) void rope_k(const int* __restrict__ pos_ids) {
    int row = blockIdx.x;
    int t = threadIdx.x;
    int h = t >> 5, j = t & 31;
    float pos = (float)pos_ids[row];
    float fe = powf(10000.0f, -(float)j / 32.0f);
    float ramp = fminf(fmaxf(((float)j - 10.0f) / 13.0f, 0.f), 1.f);
    float invf = (fe / 40.0f) * ramp + fe * (1.0f - ramp);
    float ang = pos * invf;
    float s, c;
    sincosf(ang, &s, &c);
    if (h < NHEADS) {
        __half* base = g_q16 + (size_t)row * 3072 + h * QHD + NOPE;
        float x0 = __half2float(base[2 * j]), x1 = __half2float(base[2 * j + 1]);
        __syncwarp();
        base[j]      = __float2half_rn(x0 * c - x1 * s);
        base[32 + j] = __float2half_rn(x1 * c + x0 * s);
    } else {
        const float* src = g_qab + (size_t)row * 2112 + 2048;
        float x0 = src[2 * j], x1 = src[2 * j + 1];
        __half* dst = g_kpe16 + (size_t)row * 64;
        dst[j]      = __float2half_rn(x0 * c - x1 * s);
        dst[32 + j] = __float2half_rn(x1 * c + x0 * s);
    }
}

// ==================================================================
// Flash attention, fp16 tensor cores, cp.async double-buffered K/V.
// LPT: heaviest q-tiles first via x-reversal. 2 CTAs/SM.
// ==================================================================
#define QPH 200
#define VPH 136
#define PPH 72
#define KT_H (64*QPH)
#define VT_H (64*VPH)
#define FLASH_SMEM ((64*QPH + 2*KT_H + 2*VT_H) * 2)   // 111,616 B

__global__ __launch_bounds__(128, 2) void flash_f16(float scale) {
    extern __shared__ __half smf[];
    __half* Qs = smf;
    __half* Kb = smf + 64 * QPH;
    __half* Vb = Kb + 2 * KT_H;
    const int qb = gridDim.x - 1 - blockIdx.x;   // LPT: heavy first
    const int h = blockIdx.y, b = blockIdx.z;
    const int tid = threadIdx.x;
    const int warp = tid >> 5, lane = tid & 31;
    const int g = lane >> 2, tl = lane & 3;
    const int wm = warp * 16;
    const size_t bs0 = (size_t)b * SEQ;

    const uint32_t qs_s = (uint32_t)__cvta_generic_to_shared(Qs);
    const uint32_t kb_s = (uint32_t)__cvta_generic_to_shared(Kb);
    const uint32_t vb_s = (uint32_t)__cvta_generic_to_shared(Vb);

    auto stageK = [&](int buf, int kb) {
        uint32_t base = kb_s + (uint32_t)(buf * KT_H * 2);
        #pragma unroll
        for (int u = 0; u < 12; u++) {
            int idx = tid + u * 128;
            int r = idx / 24, q8 = idx % 24;
            const __half* src = (q8 < 16)
                ? &g_kv16[(bs0 + kb * 64 + r) * 4096 + h * 256 + q8 * 8]
                : &g_kpe16[(bs0 + kb * 64 + r) * 64 + (q8 - 16) * 8];
            cp_async16(base + (r * QPH + q8 * 8) * 2, src, true);
        }
    };
    auto stageV = [&](int buf, int kb) {
        uint32_t base = vb_s + (uint32_t)(buf * VT_H * 2);
        #pragma unroll
        for (int u = 0; u < 8; u++) {
            int idx = tid + u * 128;
            int r = idx >> 4, c8 = (idx & 15) * 8;
            cp_async16(base + (r * VPH + c8) * 2,
                       &g_kv16[(bs0 + kb * 64 + r) * 4096 + h * 256 + NOPE + c8], true);
        }
    };

    #pragma unroll
    for (int u = 0; u < 12; u++) {
        int idx = tid + u * 128;
        int r = idx / 24, q8 = (idx % 24) * 8;
        cp_async16(qs_s + (r * QPH + q8) * 2,
                   &g_q16[(bs0 + qb * 64 + r) * 3072 + h * QHD + q8], true);
    }
    stageK(0, 0);
    stageV(0, 0);
    asm volatile("cp.async.commit_group;");

    float m_i[2] = {-1e30f, -1e30f};
    float l_i[2] = {0.f, 0.f};
    float acc_o[16][4];
    #pragma unroll
    for (int nt = 0; nt < 16; nt++)
        #pragma unroll
        for (int v = 0; v < 4; v++) acc_o[nt][v] = 0.f;

    const int row0 = qb * 64 + wm + g;
    const int lq = lane >> 3, lrl = lane & 7;

    for (int kb = 0; kb <= qb; kb++) {
        const int cur = kb & 1;
        asm volatile("cp.async.wait_group 0;");
        __syncthreads();
        if (kb < qb) {
            stageK(cur ^ 1, kb + 1);
            stageV(cur ^ 1, kb + 1);
            asm volatile("cp.async.commit_group;");
        }
        const __half* Ks = Kb + cur * KT_H;
        const uint32_t vcur = vb_s + (uint32_t)(cur * VT_H * 2);
        __half* Ps = Kb + cur * KT_H;

        float acc_s[8][4];
        #pragma unroll
        for (int nt = 0; nt < 8; nt++)
            #pragma unroll
            for (int v = 0; v < 4; v++) acc_s[nt][v] = 0.f;

        #pragma unroll
        for (int ks = 0; ks < 12; ks++) {
            const int kbh = ks * 16;
            uint32_t afr[4];
            afr[0] = *(const uint32_t*)&Qs[(wm + g) * QPH + kbh + 2 * tl];
            afr[1] = *(const uint32_t*)&Qs[(wm + g + 8) * QPH + kbh + 2 * tl];
            afr[2] = *(const uint32_t*)&Qs[(wm + g) * QPH + kbh + 8 + 2 * tl];
            afr[3] = *(const uint32_t*)&Qs[(wm + g + 8) * QPH + kbh + 8 + 2 * tl];
            #pragma unroll
            for (int nt = 0; nt < 8; nt++) {
                uint32_t bfr[2];
                bfr[0] = *(const uint32_t*)&Ks[(nt * 8 + g) * QPH + kbh + 2 * tl];
                bfr[1] = *(const uint32_t*)&Ks[(nt * 8 + g) * QPH + kbh + 8 + 2 * tl];
                mma_f16(acc_s[nt], afr, bfr);
            }
        }

        const bool diag = (kb == qb);
        float rmax0 = -1e30f, rmax1 = -1e30f;
        #pragma unroll
        for (int nt = 0; nt < 8; nt++) {
            int c0 = kb * 64 + nt * 8 + 2 * tl, c1 = c0 + 1;
            float s0 = acc_s[nt][0] * scale, s1 = acc_s[nt][1] * scale;
            float s2 = acc_s[nt][2] * scale, s3 = acc_s[nt][3] * scale;
            if (diag) {
                if (c0 > row0) s0 = -1e30f;
                if (c1 > row0) s1 = -1e30f;
                if (c0 > row0 + 8) s2 = -1e30f;
                if (c1 > row0 + 8) s3 = -1e30f;
            }
            acc_s[nt][0] = s0; acc_s[nt][1] = s1;
            acc_s[nt][2] = s2; acc_s[nt][3] = s3;
            rmax0 = fmaxf(rmax0, fmaxf(s0, s1));
            rmax1 = fmaxf(rmax1, fmaxf(s2, s3));
        }
        #pragma unroll
        for (int off = 1; off <= 2; off <<= 1) {
            rmax0 = fmaxf(rmax0, __shfl_xor_sync(0xffffffffu, rmax0, off));
            rmax1 = fmaxf(rmax1, __shfl_xor_sync(0xffffffffu, rmax1, off));
        }
        float mn0 = fmaxf(m_i[0], rmax0), mn1 = fmaxf(m_i[1], rmax1);
        float al0 = __expf(m_i[0] - mn0), al1 = __expf(m_i[1] - mn1);
        float p_r[8][4];
        float rs0 = 0.f, rs1 = 0.f;
        #pragma unroll
        for (int nt = 0; nt < 8; nt++) {
            p_r[nt][0] = __expf(acc_s[nt][0] - mn0);
            p_r[nt][1] = __expf(acc_s[nt][1] - mn0);
            p_r[nt][2] = __expf(acc_s[nt][2] - mn1);
            p_r[nt][3] = __expf(acc_s[nt][3] - mn1);
            rs0 += p_r[nt][0] + p_r[nt][1];
            rs1 += p_r[nt][2] + p_r[nt][3];
        }
        #pragma unroll
        for (int off = 1; off <= 2; off <<= 1) {
            rs0 += __shfl_xor_sync(0xffffffffu, rs0, off);
            rs1 += __shfl_xor_sync(0xffffffffu, rs1, off);
        }
        l_i[0] = l_i[0] * al0 + rs0;
        l_i[1] = l_i[1] * al1 + rs1;
        m_i[0] = mn0; m_i[1] = mn1;
        #pragma unroll
        for (int nt = 0; nt < 16; nt++) {
            acc_o[nt][0] *= al0; acc_o[nt][1] *= al0;
            acc_o[nt][2] *= al1; acc_o[nt][3] *= al1;
        }

        __syncthreads();
        #pragma unroll
        for (int nt = 0; nt < 8; nt++) {
            *(half2*)&Ps[(wm + g) * PPH + nt * 8 + 2 * tl] =
                __floats2half2_rn(p_r[nt][0], p_r[nt][1]);
            *(half2*)&Ps[(wm + g + 8) * PPH + nt * 8 + 2 * tl] =
                __floats2half2_rn(p_r[nt][2], p_r[nt][3]);
        }
        __syncwarp();

        #pragma unroll
        for (int ks = 0; ks < 4; ks++) {
            const int kbh = ks * 16;
            uint32_t afr[4];
            afr[0] = *(const uint32_t*)&Ps[(wm + g) * PPH + kbh + 2 * tl];
            afr[1] = *(const uint32_t*)&Ps[(wm + g + 8) * PPH + kbh + 2 * tl];
            afr[2] = *(const uint32_t*)&Ps[(wm + g) * PPH + kbh + 8 + 2 * tl];
            afr[3] = *(const uint32_t*)&Ps[(wm + g + 8) * PPH + kbh + 8 + 2 * tl];
            #pragma unroll
            for (int p = 0; p < 8; p++) {
                uint32_t maddr = vcur +
                    (uint32_t)(((kbh + (lq & 1) * 8 + lrl) * VPH +
                                (p * 2 + (lq >> 1)) * 8) * 2);
                uint32_t b0, b1, b2, b3;
                asm volatile(
                    "ldmatrix.sync.aligned.m8n8.x4.trans.shared.b16 "
                    "{%0,%1,%2,%3}, [%4];"
                    : "=r"(b0), "=r"(b1), "=r"(b2), "=r"(b3) : "r"(maddr));
                uint32_t bfr0[2] = {b0, b1};
                uint32_t bfr1[2] = {b2, b3};
                mma_f16(acc_o[2 * p],     afr, bfr0);
                mma_f16(acc_o[2 * p + 1], afr, bfr1);
            }
        }
    }

    float inv0 = 1.0f / l_i[0], inv1 = 1.0f / l_i[1];
    size_t r0 = (bs0 + qb * 64 + wm + g) * 2048 + h * VHD;
    size_t r1 = r0 + 8 * 2048;
    #pragma unroll
    for (int nt = 0; nt < 16; nt++) {
        int cn = nt * 8 + 2 * tl;
        *(half2*)&g_attn16[r0 + cn] =
            __floats2half2_rn(acc_o[nt][0] * inv0, acc_o[nt][1] * inv0);
        *(half2*)&g_attn16[r1 + cn] =
            __floats2half2_rn(acc_o[nt][2] * inv1, acc_o[nt][3] * inv1);
    }
}

// ---------------- launch ----------------
extern "C" void kernel_launch(void* const* d_in, const int* in_sizes, int n_in,
                              void* d_out, int out_size) {
    const float* hs      = (const float*)d_in[0];
    const int*   pos     = (const int*)  d_in[1];
    const float* wq_a    = (const float*)d_in[2];
    const float* q_a_ln  = (const float*)d_in[3];
    const float* wq_b    = (const float*)d_in[4];
    const float* wkv_a   = (const float*)d_in[5];
    const float* kv_a_ln = (const float*)d_in[6];
    const float* wkv_b   = (const float*)d_in[7];
    const float* wo      = (const float*)d_in[8];
    float* out = (float*)d_out;

    float *qab;
    __half *hs16, *wab16, *wqb16, *wkvb16, *wo16, *qlo16, *cn16, *q16, *kv16, *at16;
    cudaGetSymbolAddress((void**)&qab, g_qab);
    cudaGetSymbolAddress((void**)&hs16,  g_hs16);
    cudaGetSymbolAddress((void**)&wab16, g_wab16);
    cudaGetSymbolAddress((void**)&wqb16, g_wqb16);
    cudaGetSymbolAddress((void**)&wkvb16,g_wkvb16);
    cudaGetSymbolAddress((void**)&wo16,  g_wo16);
    cudaGetSymbolAddress((void**)&qlo16, g_qlora16);
    cudaGetSymbolAddress((void**)&cn16,  g_cnorm16);
    cudaGetSymbolAddress((void**)&q16,   g_q16);
    cudaGetSymbolAddress((void**)&kv16,  g_kv16);
    cudaGetSymbolAddress((void**)&at16,  g_attn16);

    double m = 0.1 * log(40.0) + 1.0;
    float scale = (float)((1.0 / sqrt(192.0)) * m * m);

    cudaFuncSetAttribute(flash_f16, cudaFuncAttributeMaxDynamicSharedMemorySize,
                         FLASH_SMEM);
    cudaFuncSetAttribute(gemm_dual, cudaFuncAttributeMaxDynamicSharedMemorySize,
                         GEMM_SMEM);

    // [0] all fp32->fp16 conversions in one launch
    cvt_all_k<<<CVT_BLOCKS, 256>>>(hs, wq_a, wkv_a, wq_b, wkv_b, wo);

    dim3 blk(256);
    // [1] combined: [qlora | ckv | kpe] = hs @ [wq_a ; wkv_a]^T   (N=2112, fp32 out)
    gemm_dual<<<dim3(17, 32), blk, GEMM_SMEM>>>(
        hs16, wab16, qab, 2112, 2048, 0, 17,
        hs16, wab16, qab, 2112, 2048, 0);
    // [2] both rmsnorms in one launch
    rmsnorm2_k<<<dim3(ROWS, 2), 256>>>(qab, q_a_ln, kv_a_ln);
    // [3] q-GEMM (24 x-tiles, K=1536) + kv-GEMM (32 x-tiles, K=512) merged
    gemm_dual<<<dim3(24 + 32, 32), blk, GEMM_SMEM>>>(
        qlo16, wqb16, q16, 3072, 1536, 2, 24,
        cn16, wkvb16, kv16, 4096, 512, 2);
    // [4] rope (q_pe in place; k_pe -> fp16)
    rope_k<<<ROWS, 544>>>(pos);
    // [5] flash attention (LPT order)
    flash_f16<<<dim3(SEQ / 64, NHEADS, BATCH), 128, FLASH_SMEM>>>(scale);
    // [6] out = attn @ wo^T (fp32 out)
    gemm_dual<<<dim3(16, 32), blk, GEMM_SMEM>>>(
        at16, wo16, out, 2048, 2048, 0, 16,
        at16, wo16, out, 2048, 2048, 0);
}

// round 15
// speedup vs baseline: 1.0750x; 1.0750x over previous
#include <cuda_runtime.h>
#include <cuda_fp16.h>
#include <math.h>
#include <stdint.h>

#define SEQ 2048
#define BATCH 2
#define ROWS (BATCH*SEQ)   // 4096
#define NHEADS 16
#define QHD 192
#define NOPE 128
#define VHD 128

// ---------------- scratch (device globals; no allocation allowed) ----------------
__device__ float g_qab [(size_t)ROWS*2112];    // [qlora(1536) | ckv(512) | kpe(64)] fp32
__device__ __half g_hs16 [(size_t)ROWS*2048];
__device__ __half g_wab16[(size_t)2112*2048];
__device__ __half g_wqb16[(size_t)3072*1536];
__device__ __half g_wkvb16[(size_t)4096*512];
__device__ __half g_wo16 [(size_t)2048*2048];
__device__ __half g_qlora16[(size_t)ROWS*1536];
__device__ __half g_cnorm16[(size_t)ROWS*512];
__device__ __half g_q16 [(size_t)ROWS*3072];
__device__ __half g_kv16[(size_t)ROWS*4096];
__device__ __half g_kpe16[(size_t)ROWS*64];
__device__ __half g_attn16[(size_t)ROWS*2048];

__device__ __forceinline__ void mma_f16(float d[4], const uint32_t a[4],
                                        const uint32_t b[2]) {
    asm volatile(
        "mma.sync.aligned.m16n8k16.row.col.f32.f16.f16.f32 "
        "{%0,%1,%2,%3}, {%4,%5,%6,%7}, {%8,%9}, {%0,%1,%2,%3};"
        : "+f"(d[0]), "+f"(d[1]), "+f"(d[2]), "+f"(d[3])
        : "r"(a[0]), "r"(a[1]), "r"(a[2]), "r"(a[3]), "r"(b[0]), "r"(b[1]));
}

__device__ __forceinline__ void ldmx4(uint32_t r[4], uint32_t saddr) {
    asm volatile(
        "ldmatrix.sync.aligned.m8n8.x4.shared.b16 {%0,%1,%2,%3}, [%4];"
        : "=r"(r[0]), "=r"(r[1]), "=r"(r[2]), "=r"(r[3]) : "r"(saddr));
}

__device__ __forceinline__ void cp_async16(uint32_t saddr, const void* gptr, bool pred) {
    int sz = pred ? 16 : 0;
    asm volatile("cp.async.cg.shared.global [%0], [%1], 16, %2;\n"
                 :: "r"(saddr), "l"(gptr), "r"(sz));
}

// ---------------- single merged fp32->fp16 conversion over all 6 buffers ----------------
#define CVT_E0 ((size_t)ROWS*2048)
#define CVT_E1 (CVT_E0 + (size_t)1536*2048)
#define CVT_E2 (CVT_E1 + (size_t)576*2048)
#define CVT_E3 (CVT_E2 + (size_t)3072*1536)
#define CVT_E4 (CVT_E3 + (size_t)4096*512)
#define CVT_E5 (CVT_E4 + (size_t)2048*2048)
#define CVT_BLOCKS ((int)(CVT_E5 / 4 / 256))

__global__ __launch_bounds__(256) void cvt_all_k(const float* __restrict__ hs,
                                                 const float* __restrict__ wqa,
                                                 const float* __restrict__ wkva,
                                                 const float* __restrict__ wqb,
                                                 const float* __restrict__ wkvb,
                                                 const float* __restrict__ wo) {
    size_t i = ((size_t)blockIdx.x * 256 + threadIdx.x) * 4;
    const float* src; __half* dst; size_t off;
    if (i < CVT_E0)      { src = hs;   dst = g_hs16;   off = i; }
    else if (i < CVT_E1) { src = wqa;  dst = g_wab16;  off = i - CVT_E0; }
    else if (i < CVT_E2) { src = wkva; dst = g_wab16 + (size_t)1536*2048; off = i - CVT_E1; }
    else if (i < CVT_E3) { src = wqb;  dst = g_wqb16;  off = i - CVT_E2; }
    else if (i < CVT_E4) { src = wkvb; dst = g_wkvb16; off = i - CVT_E3; }
    else                 { src = wo;   dst = g_wo16;   off = i - CVT_E4; }
    float4 v = *(const float4*)(src + off);
    half2* y2 = (half2*)(dst + off);
    y2[0] = __floats2half2_rn(v.x, v.y);
    y2[1] = __floats2half2_rn(v.z, v.w);
}

// ==================================================================
// FP16 dual-GEMM with ldmatrix fragment loads.
// 128x128 tile, BK=64, 3-stage cp.async, 256 threads (8 warps 4m x 2n,
// warp tile 32x64), 2 CTAs/SM. mode: 0=fp32 out, 2=fp16 out.
// ==================================================================
#define HP 72
#define AT_H (128*HP)
#define BT_H (128*HP)
#define ST_H (AT_H + BT_H)
#define GEMM_SMEM (3*ST_H*2)   // 110,592 B -> 2 CTAs/SM

__global__ __launch_bounds__(256, 2) void gemm_dual(
    const __half* __restrict__ A0, const __half* __restrict__ B0,
    void* __restrict__ C0, int N0, int K0, int mode0, int nx0,
    const __half* __restrict__ A1, const __half* __restrict__ B1,
    void* __restrict__ C1, int N1, int K1, int mode1)
{
    extern __shared__ __half smh[];
    const int tid = threadIdx.x;
    const int warp = tid >> 5, lane = tid & 31;
    const int wm = (warp & 3) * 32, wn = (warp >> 2) * 64;
    const int g = lane >> 2, tl = lane & 3;
    const int grp = lane >> 3, lr = lane & 7;   // ldmatrix addressing

    const bool second = ((int)blockIdx.x >= nx0);
    const __half* A = second ? A1 : A0;
    const __half* B = second ? B1 : B0;
    void* C   = second ? C1 : C0;
    const int N    = second ? N1 : N0;
    const int K    = second ? K1 : K0;
    const int mode = second ? mode1 : mode0;
    const int m0 = blockIdx.y * 128;
    const int n0 = (second ? (int)blockIdx.x - nx0 : (int)blockIdx.x) * 128;

    const uint32_t smbase = (uint32_t)__cvta_generic_to_shared(smh);

    float acc[2][8][4];
    #pragma unroll
    for (int i = 0; i < 2; i++)
        #pragma unroll
        for (int j = 0; j < 8; j++)
            #pragma unroll
            for (int v = 0; v < 4; v++) acc[i][j][v] = 0.f;

    const int T = K / 64;

    auto issue = [&](int stage, int t) {
        const int k0 = t * 64;
        uint32_t ab = smbase + (uint32_t)(stage * ST_H * 2);
        uint32_t bb = ab + AT_H * 2;
        #pragma unroll
        for (int u = 0; u < 4; u++) {
            int seg = tid + u * 256;
            int row = seg >> 3, gq = (seg & 7) * 8;
            cp_async16(ab + (row * HP + gq) * 2,
                       A + (size_t)(m0 + row) * K + k0 + gq, true);
            int nr = n0 + row;
            cp_async16(bb + (row * HP + gq) * 2,
                       B + (size_t)(nr < N ? nr : 0) * K + k0 + gq, nr < N);
        }
        asm volatile("cp.async.commit_group;");
    };

    issue(0, 0);
    if (T > 1) issue(1, 1); else asm volatile("cp.async.commit_group;");

    for (int t = 0; t < T; t++) {
        asm volatile("cp.async.wait_group 1;");
        __syncthreads();
        if (t + 2 < T) issue((t + 2) % 3, t + 2);
        else asm volatile("cp.async.commit_group;");

        uint32_t abase = smbase + (uint32_t)((t % 3) * ST_H * 2);
        uint32_t bbase = abase + AT_H * 2;
        #pragma unroll
        for (int ks = 0; ks < 4; ks++) {
            const int kb = ks * 16;
            uint32_t afr[2][4], bfr[8][2];
            // A fragments: one ldmatrix.x4 per 16-row m-tile
            #pragma unroll
            for (int mt = 0; mt < 2; mt++) {
                int row = wm + mt * 16 + ((grp & 1) << 3) + lr;
                int col = kb + ((grp & 2) << 2);
                ldmx4(afr[mt], abase + (uint32_t)((row * HP + col) * 2));
            }
            // B fragments: one ldmatrix.x4 per pair of 8-col n-tiles
            #pragma unroll
            for (int p = 0; p < 4; p++) {
                int row = wn + p * 16 + ((grp & 2) << 2) + lr;
                int col = kb + ((grp & 1) << 3);
                uint32_t r4[4];
                ldmx4(r4, bbase + (uint32_t)((row * HP + col) * 2));
                bfr[2 * p][0] = r4[0]; bfr[2 * p][1] = r4[1];
                bfr[2 * p + 1][0] = r4[2]; bfr[2 * p + 1][1] = r4[3];
            }
            #pragma unroll
            for (int mt = 0; mt < 2; mt++)
                #pragma unroll
                for (int nt = 0; nt < 8; nt++)
                    mma_f16(acc[mt][nt], afr[mt], bfr[nt]);
        }
    }

    #pragma unroll
    for (int mt = 0; mt < 2; mt++) {
        int r0 = m0 + wm + mt * 16 + g;
        #pragma unroll
        for (int nt = 0; nt < 8; nt++) {
            int cn = n0 + wn + nt * 8 + 2 * tl;
            if (cn < N) {
                float v0 = acc[mt][nt][0], v1 = acc[mt][nt][1];
                float v2 = acc[mt][nt][2], v3 = acc[mt][nt][3];
                if (mode == 2) {
                    __half* Ch = (__half*)C;
                    *(half2*)&Ch[(size_t)r0 * N + cn]       = __floats2half2_rn(v0, v1);
                    *(half2*)&Ch[(size_t)(r0 + 8) * N + cn] = __floats2half2_rn(v2, v3);
                } else {
                    float* Cf = (float*)C;
                    *(float2*)&Cf[(size_t)r0 * N + cn]       = make_float2(v0, v1);
                    *(float2*)&Cf[(size_t)(r0 + 8) * N + cn] = make_float2(v2, v3);
                }
            }
        }
    }
}

// ---------------- merged RMSNorm: y=0 -> qlora(1536), y=1 -> ckv(512) ----------------
__global__ __launch_bounds__(256) void rmsnorm2_k(const float* __restrict__ qab,
                                                  const float* __restrict__ w0,
                                                  const float* __restrict__ w1) {
    int row = blockIdx.x;
    int which = blockIdx.y;
    const float* x = qab + (size_t)row * 2112 + (which ? 1536 : 0);
    const float* w = which ? w1 : w0;
    int W = which ? 512 : 1536;
    __half* Y = which ? (g_cnorm16 + (size_t)row * 512)
                      : (g_qlora16 + (size_t)row * 1536);
    float ss = 0.f;
    for (int i = threadIdx.x; i < W; i += 256) { float v = x[i]; ss += v * v; }
    __shared__ float red[256];
    red[threadIdx.x] = ss;
    __syncthreads();
    for (int s = 128; s > 0; s >>= 1) {
        if (threadIdx.x < s) red[threadIdx.x] += red[threadIdx.x + s];
        __syncthreads();
    }
    float inv = rsqrtf(red[0] / (float)W + 1e-6f);
    for (int i = threadIdx.x; i < W; i += 256)
        Y[i] = __float2half_rn(w[i] * (x[i] * inv));
}

// ---------------- YaRN RoPE (fp16 q in place; kpe fp32->fp16) ----------------
__global__ __launch_bounds__(544) void rope_k(const int* __restrict__ pos_ids) {
    int row = blockIdx.x;
    int t = threadIdx.x;
    int h = t >> 5, j = t & 31;
    float pos = (float)pos_ids[row];
    float fe = powf(10000.0f, -(float)j / 32.0f);
    float ramp = fminf(fmaxf(((float)j - 10.0f) / 13.0f, 0.f), 1.f);
    float invf = (fe / 40.0f) * ramp + fe * (1.0f - ramp);
    float ang = pos * invf;
    float s, c;
    sincosf(ang, &s, &c);
    if (h < NHEADS) {
        __half* base = g_q16 + (size_t)row * 3072 + h * QHD + NOPE;
        float x0 = __half2float(base[2 * j]), x1 = __half2float(base[2 * j + 1]);
        __syncwarp();
        base[j]      = __float2half_rn(x0 * c - x1 * s);
        base[32 + j] = __float2half_rn(x1 * c + x0 * s);
    } else {
        const float* src = g_qab + (size_t)row * 2112 + 2048;
        float x0 = src[2 * j], x1 = src[2 * j + 1];
        __half* dst = g_kpe16 + (size_t)row * 64;
        dst[j]      = __float2half_rn(x0 * c - x1 * s);
        dst[32 + j] = __float2half_rn(x1 * c + x0 * s);
    }
}

// ==================================================================
// Flash attention, fp16 tensor cores, ldmatrix fragment loads,
// cp.async double-buffered K/V, LPT ordering, 2 CTAs/SM.
// ==================================================================
#define QPH 200
#define VPH 136
#define PPH 72
#define KT_H (64*QPH)
#define VT_H (64*VPH)
#define FLASH_SMEM ((64*QPH + 2*KT_H + 2*VT_H) * 2)   // 111,616 B

__global__ __launch_bounds__(128, 2) void flash_f16(float scale) {
    extern __shared__ __half smf[];
    __half* Qs = smf;
    __half* Kb = smf + 64 * QPH;
    __half* Vb = Kb + 2 * KT_H;
    const int qb = gridDim.x - 1 - blockIdx.x;   // LPT: heavy first
    const int h = blockIdx.y, b = blockIdx.z;
    const int tid = threadIdx.x;
    const int warp = tid >> 5, lane = tid & 31;
    const int g = lane >> 2, tl = lane & 3;
    const int grp = lane >> 3, lr = lane & 7;
    const int wm = warp * 16;
    const size_t bs0 = (size_t)b * SEQ;

    const uint32_t qs_s = (uint32_t)__cvta_generic_to_shared(Qs);
    const uint32_t kb_s = (uint32_t)__cvta_generic_to_shared(Kb);
    const uint32_t vb_s = (uint32_t)__cvta_generic_to_shared(Vb);

    auto stageK = [&](int buf, int kb) {
        uint32_t base = kb_s + (uint32_t)(buf * KT_H * 2);
        #pragma unroll
        for (int u = 0; u < 12; u++) {
            int idx = tid + u * 128;
            int r = idx / 24, q8 = idx % 24;
            const __half* src = (q8 < 16)
                ? &g_kv16[(bs0 + kb * 64 + r) * 4096 + h * 256 + q8 * 8]
                : &g_kpe16[(bs0 + kb * 64 + r) * 64 + (q8 - 16) * 8];
            cp_async16(base + (r * QPH + q8 * 8) * 2, src, true);
        }
    };
    auto stageV = [&](int buf, int kb) {
        uint32_t base = vb_s + (uint32_t)(buf * VT_H * 2);
        #pragma unroll
        for (int u = 0; u < 8; u++) {
            int idx = tid + u * 128;
            int r = idx >> 4, c8 = (idx & 15) * 8;
            cp_async16(base + (r * VPH + c8) * 2,
                       &g_kv16[(bs0 + kb * 64 + r) * 4096 + h * 256 + NOPE + c8], true);
        }
    };

    #pragma unroll
    for (int u = 0; u < 12; u++) {
        int idx = tid + u * 128;
        int r = idx / 24, q8 = (idx % 24) * 8;
        cp_async16(qs_s + (r * QPH + q8) * 2,
                   &g_q16[(bs0 + qb * 64 + r) * 3072 + h * QHD + q8], true);
    }
    stageK(0, 0);
    stageV(0, 0);
    asm volatile("cp.async.commit_group;");

    float m_i[2] = {-1e30f, -1e30f};
    float l_i[2] = {0.f, 0.f};
    float acc_o[16][4];
    #pragma unroll
    for (int nt = 0; nt < 16; nt++)
        #pragma unroll
        for (int v = 0; v < 4; v++) acc_o[nt][v] = 0.f;

    const int row0 = qb * 64 + wm + g;

    for (int kb = 0; kb <= qb; kb++) {
        const int cur = kb & 1;
        asm volatile("cp.async.wait_group 0;");
        __syncthreads();
        if (kb < qb) {
            stageK(cur ^ 1, kb + 1);
            stageV(cur ^ 1, kb + 1);
            asm volatile("cp.async.commit_group;");
        }
        const uint32_t kcur = kb_s + (uint32_t)(cur * KT_H * 2);
        const uint32_t vcur = vb_s + (uint32_t)(cur * VT_H * 2);
        __half* Ps = Kb + cur * KT_H;
        const uint32_t ps_s = kcur;

        float acc_s[8][4];
        #pragma unroll
        for (int nt = 0; nt < 8; nt++)
            #pragma unroll
            for (int v = 0; v < 4; v++) acc_s[nt][v] = 0.f;

        #pragma unroll
        for (int ks = 0; ks < 12; ks++) {
            const int kbh = ks * 16;
            uint32_t afr[4];
            {
                int row = wm + ((grp & 1) << 3) + lr;
                int col = kbh + ((grp & 2) << 2);
                ldmx4(afr, qs_s + (uint32_t)((row * QPH + col) * 2));
            }
            #pragma unroll
            for (int p = 0; p < 4; p++) {
                int row = p * 16 + ((grp & 2) << 2) + lr;
                int col = kbh + ((grp & 1) << 3);
                uint32_t r4[4];
                ldmx4(r4, kcur + (uint32_t)((row * QPH + col) * 2));
                uint32_t b0[2] = {r4[0], r4[1]};
                uint32_t b1[2] = {r4[2], r4[3]};
                mma_f16(acc_s[2 * p], afr, b0);
                mma_f16(acc_s[2 * p + 1], afr, b1);
            }
        }

        const bool diag = (kb == qb);
        float rmax0 = -1e30f, rmax1 = -1e30f;
        #pragma unroll
        for (int nt = 0; nt < 8; nt++) {
            int c0 = kb * 64 + nt * 8 + 2 * tl, c1 = c0 + 1;
            float s0 = acc_s[nt][0] * scale, s1 = acc_s[nt][1] * scale;
            float s2 = acc_s[nt][2] * scale, s3 = acc_s[nt][3] * scale;
            if (diag) {
                if (c0 > row0) s0 = -1e30f;
                if (c1 > row0) s1 = -1e30f;
                if (c0 > row0 + 8) s2 = -1e30f;
                if (c1 > row0 + 8) s3 = -1e30f;
            }
            acc_s[nt][0] = s0; acc_s[nt][1] = s1;
            acc_s[nt][2] = s2; acc_s[nt][3] = s3;
            rmax0 = fmaxf(rmax0, fmaxf(s0, s1));
            rmax1 = fmaxf(rmax1, fmaxf(s2, s3));
        }
        #pragma unroll
        for (int off = 1; off <= 2; off <<= 1) {
            rmax0 = fmaxf(rmax0, __shfl_xor_sync(0xffffffffu, rmax0, off));
            rmax1 = fmaxf(rmax1, __shfl_xor_sync(0xffffffffu, rmax1, off));
        }
        float mn0 = fmaxf(m_i[0], rmax0), mn1 = fmaxf(m_i[1], rmax1);
        float al0 = __expf(m_i[0] - mn0), al1 = __expf(m_i[1] - mn1);
        float p_r[8][4];
        float rs0 = 0.f, rs1 = 0.f;
        #pragma unroll
        for (int nt = 0; nt < 8; nt++) {
            p_r[nt][0] = __expf(acc_s[nt][0] - mn0);
            p_r[nt][1] = __expf(acc_s[nt][1] - mn0);
            p_r[nt][2] = __expf(acc_s[nt][2] - mn1);
            p_r[nt][3] = __expf(acc_s[nt][3] - mn1);
            rs0 += p_r[nt][0] + p_r[nt][1];
            rs1 += p_r[nt][2] + p_r[nt][3];
        }
        #pragma unroll
        for (int off = 1; off <= 2; off <<= 1) {
            rs0 += __shfl_xor_sync(0xffffffffu, rs0, off);
            rs1 += __shfl_xor_sync(0xffffffffu, rs1, off);
        }
        l_i[0] = l_i[0] * al0 + rs0;
        l_i[1] = l_i[1] * al1 + rs1;
        m_i[0] = mn0; m_i[1] = mn1;
        #pragma unroll
        for (int nt = 0; nt < 16; nt++) {
            acc_o[nt][0] *= al0; acc_o[nt][1] *= al0;
            acc_o[nt][2] *= al1; acc_o[nt][3] *= al1;
        }

        __syncthreads();
        #pragma unroll
        for (int nt = 0; nt < 8; nt++) {
            *(half2*)&Ps[(wm + g) * PPH + nt * 8 + 2 * tl] =
                __floats2half2_rn(p_r[nt][0], p_r[nt][1]);
            *(half2*)&Ps[(wm + g + 8) * PPH + nt * 8 + 2 * tl] =
                __floats2half2_rn(p_r[nt][2], p_r[nt][3]);
        }
        __syncwarp();

        #pragma unroll
        for (int ks = 0; ks < 4; ks++) {
            const int kbh = ks * 16;
            uint32_t afr[4];
            {
                int row = wm + ((grp & 1) << 3) + lr;
                int col = kbh + ((grp & 2) << 2);
                ldmx4(afr, ps_s + (uint32_t)((row * PPH + col) * 2));
            }
            #pragma unroll
            for (int p = 0; p < 8; p++) {
                uint32_t maddr = vcur +
                    (uint32_t)(((kbh + ((grp & 1) << 3) + lr) * VPH +
                                (p * 2 + (grp >> 1)) * 8) * 2);
                uint32_t b0, b1, b2, b3;
                asm volatile(
                    "ldmatrix.sync.aligned.m8n8.x4.trans.shared.b16 "
                    "{%0,%1,%2,%3}, [%4];"
                    : "=r"(b0), "=r"(b1), "=r"(b2), "=r"(b3) : "r"(maddr));
                uint32_t bfr0[2] = {b0, b1};
                uint32_t bfr1[2] = {b2, b3};
                mma_f16(acc_o[2 * p],     afr, bfr0);
                mma_f16(acc_o[2 * p + 1], afr, bfr1);
            }
        }
    }

    float inv0 = 1.0f / l_i[0], inv1 = 1.0f / l_i[1];
    size_t r0 = (bs0 + qb * 64 + wm + g) * 2048 + h * VHD;
    size_t r1 = r0 + 8 * 2048;
    #pragma unroll
    for (int nt = 0; nt < 16; nt++) {
        int cn = nt * 8 + 2 * tl;
        *(half2*)&g_attn16[r0 + cn] =
            __floats2half2_rn(acc_o[nt][0] * inv0, acc_o[nt][1] * inv0);
        *(half2*)&g_attn16[r1 + cn] =
            __floats2half2_rn(acc_o[nt][2] * inv1, acc_o[nt][3] * inv1);
    }
}

// ---------------- launch ----------------
extern "C" void kernel_launch(void* const* d_in, const int* in_sizes, int n_in,
                              void* d_out, int out_size) {
    const float* hs      = (const float*)d_in[0];
    const int*   pos     = (const int*)  d_in[1];
    const float* wq_a    = (const float*)d_in[2];
    const float* q_a_ln  = (const float*)d_in[3];
    const float* wq_b    = (const float*)d_in[4];
    const float* wkv_a   = (const float*)d_in[5];
    const float* kv_a_ln = (const float*)d_in[6];
    const float* wkv_b   = (const float*)d_in[7];
    const float* wo      = (const float*)d_in[8];
    float* out = (float*)d_out;

    float *qab;
    __half *hs16, *wab16, *wqb16, *wkvb16, *wo16, *qlo16, *cn16, *q16, *kv16, *at16;
    cudaGetSymbolAddress((void**)&qab, g_qab);
    cudaGetSymbolAddress((void**)&hs16,  g_hs16);
    cudaGetSymbolAddress((void**)&wab16, g_wab16);
    cudaGetSymbolAddress((void**)&wqb16, g_wqb16);
    cudaGetSymbolAddress((void**)&wkvb16,g_wkvb16);
    cudaGetSymbolAddress((void**)&wo16,  g_wo16);
    cudaGetSymbolAddress((void**)&qlo16, g_qlora16);
    cudaGetSymbolAddress((void**)&cn16,  g_cnorm16);
    cudaGetSymbolAddress((void**)&q16,   g_q16);
    cudaGetSymbolAddress((void**)&kv16,  g_kv16);
    cudaGetSymbolAddress((void**)&at16,  g_attn16);

    double m = 0.1 * log(40.0) + 1.0;
    float scale = (float)((1.0 / sqrt(192.0)) * m * m);

    cudaFuncSetAttribute(flash_f16, cudaFuncAttributeMaxDynamicSharedMemorySize,
                         FLASH_SMEM);
    cudaFuncSetAttribute(gemm_dual, cudaFuncAttributeMaxDynamicSharedMemorySize,
                         GEMM_SMEM);

    // [0] all fp32->fp16 conversions in one launch
    cvt_all_k<<<CVT_BLOCKS, 256>>>(hs, wq_a, wkv_a, wq_b, wkv_b, wo);

    dim3 blk(256);
    // [1] combined: [qlora | ckv | kpe] = hs @ [wq_a ; wkv_a]^T   (N=2112, fp32 out)
    gemm_dual<<<dim3(17, 32), blk, GEMM_SMEM>>>(
        hs16, wab16, qab, 2112, 2048, 0, 17,
        hs16, wab16, qab, 2112, 2048, 0);
    // [2] both rmsnorms in one launch
    rmsnorm2_k<<<dim3(ROWS, 2), 256>>>(qab, q_a_ln, kv_a_ln);
    // [3] q-GEMM (24 x-tiles, K=1536) + kv-GEMM (32 x-tiles, K=512) merged
    gemm_dual<<<dim3(24 + 32, 32), blk, GEMM_SMEM>>>(
        qlo16, wqb16, q16, 3072, 1536, 2, 24,
        cn16, wkvb16, kv16, 4096, 512, 2);
    // [4] rope (q_pe in place; k_pe -> fp16)
    rope_k<<<ROWS, 544>>>(pos);
    // [5] flash attention (LPT order)
    flash_f16<<<dim3(SEQ / 64, NHEADS, BATCH), 128, FLASH_SMEM>>>(scale);
    // [6] out = attn @ wo^T (fp32 out)
    gemm_dual<<<dim3(16, 32), blk, GEMM_SMEM>>>(
        at16, wo16, out, 2048, 2048, 0, 16,
        at16, wo16, out, 2048, 2048, 0);
}